// round 12
// baseline (speedup 1.0000x reference)
#include <cuda_runtime.h>
#include <cuda_bf16.h>
#include <cstdint>

#define NN 100000
#define EE 1600000
#define PP 200000

// Scratch (allocation-free rule: __device__ globals)
__device__ float g_h0[NN * 64];   // 2x + scatter_sum
__device__ float g_h [NN * 64];   // node embedding after MLP
__device__ float g_u [NN * 64];   // h @ (A+C)
__device__ float g_v [NN * 64];   // h @ (A+D)

// ---------------------------------------------------------------------------
// K0: h0 = 2*x  (vectorized)
__global__ void k_init(const float* __restrict__ x) {
    int i = blockIdx.x * blockDim.x + threadIdx.x;
    if (i < NN * 16) {
        float4 v = reinterpret_cast<const float4*>(x)[i];
        v.x += v.x; v.y += v.y; v.z += v.z; v.w += v.w;
        reinterpret_cast<float4*>(g_h0)[i] = v;
    }
}

// ---------------------------------------------------------------------------
// K1: scatter  h0[dst] += x[src].  16 lanes per edge (one float4 chunk each).
__global__ void __launch_bounds__(256) k_scatter(const float* __restrict__ x,
                                                 const int* __restrict__ ei) {
    int u = blockIdx.x * blockDim.x + threadIdx.x;
    if (u >= EE * 16) return;
    int e = u >> 4;
    int c = u & 15;
    int src = ei[e];
    int dst = ei[EE + e];
    float4 val = reinterpret_cast<const float4*>(x)[src * 16 + c];
    float* p = &g_h0[dst * 64 + c * 4];
    asm volatile("red.global.add.v4.f32 [%0], {%1, %2, %3, %4};"
                 :: "l"(p), "f"(val.x), "f"(val.y), "f"(val.z), "f"(val.w)
                 : "memory");
}

// ---------------------------------------------------------------------------
// K2: fused node MLP + decoder precompute (unchanged from R10).
__global__ void __launch_bounds__(128) k_mlp_uv(
    const float* __restrict__ w1, const float* __restrict__ b1,
    const float* __restrict__ w2, const float* __restrict__ b2,
    const float* __restrict__ dw1)
{
    __shared__ float4 B1q[1024];
    __shared__ float4 B2q[1024];
    __shared__ float  stage[4][8][64];
    int tid = threadIdx.x;

    for (int i = tid; i < 1024; i += 128) {
        int k4 = i >> 6, out = i & 63;
        int kb = k4 * 4 * 64 + out;
        B1q[i] = make_float4(w1[kb], w1[kb + 64], w1[kb + 128], w1[kb + 192]);
        B2q[i] = make_float4(w2[kb], w2[kb + 64], w2[kb + 128], w2[kb + 192]);
    }

    int wid  = tid >> 5;
    int lane = tid & 31;
    int base = blockIdx.x * 32 + wid * 8;

    #pragma unroll
    for (int t = 0; t < 8; t++) {
        int node = base + t;
        if (node < NN) {
            stage[wid][t][lane]      = g_h0[node * 64 + lane];
            stage[wid][t][lane + 32] = g_h0[node * 64 + lane + 32];
        }
    }
    __syncthreads();

    float bb0 = b1[lane], bb1 = b1[lane + 32];
    float a0[8], a1[8];
    #pragma unroll
    for (int t = 0; t < 8; t++) { a0[t] = bb0; a1[t] = bb1; }

    #pragma unroll
    for (int k4 = 0; k4 < 16; k4++) {
        float4 w0 = B1q[k4 * 64 + lane];
        float4 w1v = B1q[k4 * 64 + lane + 32];
        #pragma unroll
        for (int t = 0; t < 8; t++) {
            float4 m = *reinterpret_cast<const float4*>(&stage[wid][t][k4 * 4]);
            a0[t] = fmaf(m.x, w0.x, a0[t]);  a1[t] = fmaf(m.x, w1v.x, a1[t]);
            a0[t] = fmaf(m.y, w0.y, a0[t]);  a1[t] = fmaf(m.y, w1v.y, a1[t]);
            a0[t] = fmaf(m.z, w0.z, a0[t]);  a1[t] = fmaf(m.z, w1v.z, a1[t]);
            a0[t] = fmaf(m.w, w0.w, a0[t]);  a1[t] = fmaf(m.w, w1v.w, a1[t]);
        }
    }
    __syncwarp();
    #pragma unroll
    for (int t = 0; t < 8; t++) {
        stage[wid][t][lane]      = fmaxf(a0[t], 0.0f);
        stage[wid][t][lane + 32] = fmaxf(a1[t], 0.0f);
    }
    __syncwarp();

    bb0 = b2[lane]; bb1 = b2[lane + 32];
    #pragma unroll
    for (int t = 0; t < 8; t++) { a0[t] = bb0; a1[t] = bb1; }

    #pragma unroll
    for (int k4 = 0; k4 < 16; k4++) {
        float4 w0 = B2q[k4 * 64 + lane];
        float4 w1v = B2q[k4 * 64 + lane + 32];
        #pragma unroll
        for (int t = 0; t < 8; t++) {
            float4 m = *reinterpret_cast<const float4*>(&stage[wid][t][k4 * 4]);
            a0[t] = fmaf(m.x, w0.x, a0[t]);  a1[t] = fmaf(m.x, w1v.x, a1[t]);
            a0[t] = fmaf(m.y, w0.y, a0[t]);  a1[t] = fmaf(m.y, w1v.y, a1[t]);
            a0[t] = fmaf(m.z, w0.z, a0[t]);  a1[t] = fmaf(m.z, w1v.z, a1[t]);
            a0[t] = fmaf(m.w, w0.w, a0[t]);  a1[t] = fmaf(m.w, w1v.w, a1[t]);
        }
    }

    #pragma unroll
    for (int t = 0; t < 8; t++) {
        a0[t] = fmaxf(a0[t], 0.0f);
        a1[t] = fmaxf(a1[t], 0.0f);
        int node = base + t;
        if (node < NN) {
            g_h[node * 64 + lane]      = a0[t];
            g_h[node * 64 + lane + 32] = a1[t];
        }
    }
    __syncthreads();
    #pragma unroll
    for (int t = 0; t < 8; t++) {
        stage[wid][t][lane]      = a0[t];
        stage[wid][t][lane + 32] = a1[t];
    }
    for (int i = tid; i < 1024; i += 128) {
        int k4 = i >> 6, out = i & 63;
        int kb = k4 * 4 * 64 + out;
        B1q[i] = make_float4(dw1[kb]       + dw1[128 * 64 + kb],
                             dw1[kb + 64]  + dw1[128 * 64 + kb + 64],
                             dw1[kb + 128] + dw1[128 * 64 + kb + 128],
                             dw1[kb + 192] + dw1[128 * 64 + kb + 192]);
        B2q[i] = make_float4(dw1[kb]       + dw1[192 * 64 + kb],
                             dw1[kb + 64]  + dw1[192 * 64 + kb + 64],
                             dw1[kb + 128] + dw1[192 * 64 + kb + 128],
                             dw1[kb + 192] + dw1[192 * 64 + kb + 192]);
    }
    __syncthreads();

    float u0[8], u1[8], v0[8], v1[8];
    #pragma unroll
    for (int t = 0; t < 8; t++) { u0[t] = u1[t] = v0[t] = v1[t] = 0.0f; }

    #pragma unroll
    for (int k4 = 0; k4 < 16; k4++) {
        float4 c0 = B1q[k4 * 64 + lane];
        float4 c1 = B1q[k4 * 64 + lane + 32];
        float4 d0 = B2q[k4 * 64 + lane];
        float4 d1 = B2q[k4 * 64 + lane + 32];
        #pragma unroll
        for (int t = 0; t < 8; t++) {
            float4 m = *reinterpret_cast<const float4*>(&stage[wid][t][k4 * 4]);
            u0[t] = fmaf(m.x, c0.x, u0[t]);  u1[t] = fmaf(m.x, c1.x, u1[t]);
            v0[t] = fmaf(m.x, d0.x, v0[t]);  v1[t] = fmaf(m.x, d1.x, v1[t]);
            u0[t] = fmaf(m.y, c0.y, u0[t]);  u1[t] = fmaf(m.y, c1.y, u1[t]);
            v0[t] = fmaf(m.y, d0.y, v0[t]);  v1[t] = fmaf(m.y, d1.y, v1[t]);
            u0[t] = fmaf(m.z, c0.z, u0[t]);  u1[t] = fmaf(m.z, c1.z, u1[t]);
            v0[t] = fmaf(m.z, d0.z, v0[t]);  v1[t] = fmaf(m.z, d1.z, v1[t]);
            u0[t] = fmaf(m.w, c0.w, u0[t]);  u1[t] = fmaf(m.w, c1.w, u1[t]);
            v0[t] = fmaf(m.w, d0.w, v0[t]);  v1[t] = fmaf(m.w, d1.w, v1[t]);
        }
    }
    #pragma unroll
    for (int t = 0; t < 8; t++) {
        int node = base + t;
        if (node < NN) {
            g_u[node * 64 + lane]      = u0[t];
            g_u[node * 64 + lane + 32] = u1[t];
            g_v[node * 64 + lane]      = v0[t];
            g_v[node * 64 + lane + 32] = v1[t];
        }
    }
}

// ===========================================================================
// K3: pair decoder via warp-level bf16 MMA (mma.sync m16n8k16, sm_80+ PTX —
// no sm_103a-only features). Hi/lo bf16 split for the Prod @ B product; the
// u[i]+v[j]+db1 term enters the accumulator fragment in full fp32.
//   D[p][n] = Prod[p] @ B + UV[p];  out[p] = relu(D[p]) . dw2 + db2
// 128 pairs/CTA, 8 warps x 16 pairs. Padded smem strides -> conflict-free
// fragment loads (bank = 4*grp + tig permutation).
// ===========================================================================

// byte offsets in dynamic smem
#define OFF_PH  0          // ProdHi bf16 [128][72]  (stride 144B)
#define OFF_PL  18432      // ProdLo bf16 [128][72]
#define OFF_UV  36864      // UV fp32 [128][72]      (stride 288B)
#define OFF_BH  73728      // Bt hi bf16 [64][72]    (Bt[n][k], stride 144B)
#define OFF_BL  82944      // Bt lo bf16 [64][72]
#define OFF_DW2 92160      // dw2 fp32 [64]
#define PAIR_SMEM 92416

__device__ __forceinline__ void split_pack(float fx, float fy, uint32_t& hi, uint32_t& lo) {
    __nv_bfloat16 hx = __float2bfloat16(fx);
    __nv_bfloat16 hy = __float2bfloat16(fy);
    __nv_bfloat16 lx = __float2bfloat16(fx - __bfloat162float(hx));
    __nv_bfloat16 ly = __float2bfloat16(fy - __bfloat162float(hy));
    __nv_bfloat162 h2; h2.x = hx; h2.y = hy;
    __nv_bfloat162 l2; l2.x = lx; l2.y = ly;
    hi = *reinterpret_cast<uint32_t*>(&h2);
    lo = *reinterpret_cast<uint32_t*>(&l2);
}

#define MMA16816(c0, c1, c2, c3, a, b0, b1)                                  \
    asm volatile(                                                            \
        "mma.sync.aligned.m16n8k16.row.col.f32.bf16.bf16.f32 "              \
        "{%0,%1,%2,%3}, {%4,%5,%6,%7}, {%8,%9}, {%0,%1,%2,%3};"             \
        : "+f"(c0), "+f"(c1), "+f"(c2), "+f"(c3)                             \
        : "r"((a)[0]), "r"((a)[1]), "r"((a)[2]), "r"((a)[3]),                \
          "r"(b0), "r"(b1))

__global__ void __launch_bounds__(256) k_pair_mma(
    const int* __restrict__ idx,
    const float* __restrict__ dw1, const float* __restrict__ db1,
    const float* __restrict__ dw2, const float* __restrict__ db2,
    float* __restrict__ out)
{
    extern __shared__ unsigned char sm[];
    int tid = threadIdx.x;

    // ---- stage B^T hi/lo: Bt[n][k] = dw1[(64+k)*64 + n] ----
    for (int i = tid; i < 4096; i += 256) {
        int n = i >> 6, k = i & 63;
        float f = dw1[(64 + k) * 64 + n];
        __nv_bfloat16 h = __float2bfloat16(f);
        __nv_bfloat16 l = __float2bfloat16(f - __bfloat162float(h));
        *reinterpret_cast<__nv_bfloat16*>(sm + OFF_BH + n * 144 + k * 2) = h;
        *reinterpret_cast<__nv_bfloat16*>(sm + OFF_BL + n * 144 + k * 2) = l;
    }
    if (tid < 64) reinterpret_cast<float*>(sm + OFF_DW2)[tid] = dw2[tid];

    // ---- stage pairs: 2 threads per pair ----
    {
        int p_local = tid >> 1;
        int half = tid & 1;
        int p = blockIdx.x * 128 + p_local;
        int pc = p < PP ? p : PP - 1;
        int i0 = idx[pc];
        int j0 = idx[PP + pc];
        #pragma unroll
        for (int cc = 0; cc < 8; cc++) {
            int c = half * 8 + cc;
            float4 hi4 = reinterpret_cast<const float4*>(g_h)[i0 * 16 + c];
            float4 hj4 = reinterpret_cast<const float4*>(g_h)[j0 * 16 + c];
            float4 u4  = reinterpret_cast<const float4*>(g_u)[i0 * 16 + c];
            float4 v4  = reinterpret_cast<const float4*>(g_v)[j0 * 16 + c];
            float4 d4  = reinterpret_cast<const float4*>(db1)[c];
            float4 pr = make_float4(hi4.x * hj4.x, hi4.y * hj4.y,
                                    hi4.z * hj4.z, hi4.w * hj4.w);
            float4 uv = make_float4(u4.x + v4.x + d4.x, u4.y + v4.y + d4.y,
                                    u4.z + v4.z + d4.z, u4.w + v4.w + d4.w);
            uint2 ph, pl;
            split_pack(pr.x, pr.y, ph.x, pl.x);
            split_pack(pr.z, pr.w, ph.y, pl.y);
            *reinterpret_cast<uint2*> (sm + OFF_PH + p_local * 144 + c * 8)  = ph;
            *reinterpret_cast<uint2*> (sm + OFF_PL + p_local * 144 + c * 8)  = pl;
            *reinterpret_cast<float4*>(sm + OFF_UV + p_local * 288 + c * 16) = uv;
        }
    }
    __syncthreads();

    int wid  = tid >> 5;
    int lane = tid & 31;
    int grp  = lane >> 2;    // 0..7
    int tig  = lane & 3;     // 0..3
    int r0   = wid * 16 + grp;

    const uint32_t* PH  = reinterpret_cast<const uint32_t*>(sm + OFF_PH);  // stride 36 u32
    const uint32_t* PL  = reinterpret_cast<const uint32_t*>(sm + OFF_PL);
    const uint32_t* BH  = reinterpret_cast<const uint32_t*>(sm + OFF_BH);
    const uint32_t* BL  = reinterpret_cast<const uint32_t*>(sm + OFF_BL);
    const float*    UVf = reinterpret_cast<const float*>   (sm + OFF_UV);  // stride 72 f32
    const float*   sdw2 = reinterpret_cast<const float*>   (sm + OFF_DW2);

    // hoist A fragments: 4 k-steps, hi and lo
    uint32_t ah[4][4], al[4][4];
    #pragma unroll
    for (int ks = 0; ks < 4; ks++) {
        int k0 = ks * 8 + tig;                 // u32 units
        ah[ks][0] = PH[ r0      * 36 + k0];
        ah[ks][1] = PH[(r0 + 8) * 36 + k0];
        ah[ks][2] = PH[ r0      * 36 + k0 + 4];
        ah[ks][3] = PH[(r0 + 8) * 36 + k0 + 4];
        al[ks][0] = PL[ r0      * 36 + k0];
        al[ks][1] = PL[(r0 + 8) * 36 + k0];
        al[ks][2] = PL[ r0      * 36 + k0 + 4];
        al[ks][3] = PL[(r0 + 8) * 36 + k0 + 4];
    }

    float pa = 0.0f, pb = 0.0f;
    #pragma unroll
    for (int nt = 0; nt < 8; nt++) {
        int n = nt * 8 + grp;
        int cbase = nt * 8 + tig * 2;
        float2 cA = *reinterpret_cast<const float2*>(&UVf[ r0      * 72 + cbase]);
        float2 cB = *reinterpret_cast<const float2*>(&UVf[(r0 + 8) * 72 + cbase]);
        float c0 = cA.x, c1 = cA.y, c2 = cB.x, c3 = cB.y;
        #pragma unroll
        for (int ks = 0; ks < 4; ks++) {
            int kb = ks * 8 + tig;
            uint32_t bh0 = BH[n * 36 + kb], bh1 = BH[n * 36 + kb + 4];
            uint32_t bl0 = BL[n * 36 + kb], bl1 = BL[n * 36 + kb + 4];
            MMA16816(c0, c1, c2, c3, ah[ks], bh0, bh1);   // hi*hi
            MMA16816(c0, c1, c2, c3, ah[ks], bl0, bl1);   // hi*lo
            MMA16816(c0, c1, c2, c3, al[ks], bh0, bh1);   // lo*hi
        }
        float w0 = sdw2[cbase], w1 = sdw2[cbase + 1];
        pa = fmaf(fmaxf(c0, 0.0f), w0, fmaf(fmaxf(c1, 0.0f), w1, pa));
        pb = fmaf(fmaxf(c2, 0.0f), w0, fmaf(fmaxf(c3, 0.0f), w1, pb));
    }

    // reduce across the 4-thread tig group (lanes differ in bits 0,1)
    pa += __shfl_xor_sync(0xffffffffu, pa, 1);
    pa += __shfl_xor_sync(0xffffffffu, pa, 2);
    pb += __shfl_xor_sync(0xffffffffu, pb, 1);
    pb += __shfl_xor_sync(0xffffffffu, pb, 2);

    if (tig == 0) {
        float bo = db2[0];
        int pA = blockIdx.x * 128 + r0;
        int pB = pA + 8;
        if (pA < PP) out[pA] = pa + bo;
        if (pB < PP) out[pB] = pb + bo;
    }
}

// ---------------------------------------------------------------------------
extern "C" void kernel_launch(void* const* d_in, const int* in_sizes, int n_in,
                              void* d_out, int out_size) {
    const float* x   = (const float*)d_in[0];
    const int*   ei  = (const int*)  d_in[1];
    // d_in[2] = curvature (unused by the output)
    const int*   idx = (const int*)  d_in[3];
    const float* w1  = (const float*)d_in[4];
    const float* b1  = (const float*)d_in[5];
    const float* w2  = (const float*)d_in[6];
    const float* b2  = (const float*)d_in[7];
    const float* dw1 = (const float*)d_in[8];
    const float* db1 = (const float*)d_in[9];
    const float* dw2 = (const float*)d_in[10];
    const float* db2 = (const float*)d_in[11];
    float* out = (float*)d_out;

    cudaFuncSetAttribute(k_pair_mma, cudaFuncAttributeMaxDynamicSharedMemorySize,
                         PAIR_SMEM);

    k_init    <<<(NN * 16 + 255) / 256, 256>>>(x);
    k_scatter <<<(EE * 16 + 255) / 256, 256>>>(x, ei);
    k_mlp_uv  <<<(NN + 31) / 32, 128>>>(w1, b1, w2, b2, dw1);
    k_pair_mma<<<(PP + 127) / 128, 256, PAIR_SMEM>>>(idx, dw1, db1, dw2, db2, out);
}

// round 13
// speedup vs baseline: 1.1935x; 1.1935x over previous
#include <cuda_runtime.h>
#include <cuda_bf16.h>
#include <cstdint>

#define NN 100000
#define EE 1600000
#define PP 200000

// Scratch (allocation-free rule: __device__ globals)
__device__ float g_h0[NN * 64];   // 2x + scatter_sum
__device__ float g_h [NN * 64];   // node embedding after MLP
__device__ float g_u [NN * 64];   // h @ (A+C)
__device__ float g_v [NN * 64];   // h @ (A+D)

// ---------------------------------------------------------------------------
// K0: h0 = 2*x  (vectorized)
__global__ void k_init(const float* __restrict__ x) {
    int i = blockIdx.x * blockDim.x + threadIdx.x;
    if (i < NN * 16) {
        float4 v = reinterpret_cast<const float4*>(x)[i];
        v.x += v.x; v.y += v.y; v.z += v.z; v.w += v.w;
        reinterpret_cast<float4*>(g_h0)[i] = v;
    }
}

// ---------------------------------------------------------------------------
// K1: scatter  h0[dst] += x[src].  16 lanes per edge (one float4 chunk each).
__global__ void __launch_bounds__(256) k_scatter(const float* __restrict__ x,
                                                 const int* __restrict__ ei) {
    int u = blockIdx.x * blockDim.x + threadIdx.x;
    if (u >= EE * 16) return;
    int e = u >> 4;
    int c = u & 15;
    int src = ei[e];
    int dst = ei[EE + e];
    float4 val = reinterpret_cast<const float4*>(x)[src * 16 + c];
    float* p = &g_h0[dst * 64 + c * 4];
    asm volatile("red.global.add.v4.f32 [%0], {%1, %2, %3, %4};"
                 :: "l"(p), "f"(val.x), "f"(val.y), "f"(val.z), "f"(val.w)
                 : "memory");
}

// ---------------------------------------------------------------------------
// K2: fused node MLP + decoder precompute (unchanged from R10).
__global__ void __launch_bounds__(128) k_mlp_uv(
    const float* __restrict__ w1, const float* __restrict__ b1,
    const float* __restrict__ w2, const float* __restrict__ b2,
    const float* __restrict__ dw1)
{
    __shared__ float4 B1q[1024];
    __shared__ float4 B2q[1024];
    __shared__ float  stage[4][8][64];
    int tid = threadIdx.x;

    for (int i = tid; i < 1024; i += 128) {
        int k4 = i >> 6, out = i & 63;
        int kb = k4 * 4 * 64 + out;
        B1q[i] = make_float4(w1[kb], w1[kb + 64], w1[kb + 128], w1[kb + 192]);
        B2q[i] = make_float4(w2[kb], w2[kb + 64], w2[kb + 128], w2[kb + 192]);
    }

    int wid  = tid >> 5;
    int lane = tid & 31;
    int base = blockIdx.x * 32 + wid * 8;

    #pragma unroll
    for (int t = 0; t < 8; t++) {
        int node = base + t;
        if (node < NN) {
            stage[wid][t][lane]      = g_h0[node * 64 + lane];
            stage[wid][t][lane + 32] = g_h0[node * 64 + lane + 32];
        }
    }
    __syncthreads();

    float bb0 = b1[lane], bb1 = b1[lane + 32];
    float a0[8], a1[8];
    #pragma unroll
    for (int t = 0; t < 8; t++) { a0[t] = bb0; a1[t] = bb1; }

    #pragma unroll
    for (int k4 = 0; k4 < 16; k4++) {
        float4 w0 = B1q[k4 * 64 + lane];
        float4 w1v = B1q[k4 * 64 + lane + 32];
        #pragma unroll
        for (int t = 0; t < 8; t++) {
            float4 m = *reinterpret_cast<const float4*>(&stage[wid][t][k4 * 4]);
            a0[t] = fmaf(m.x, w0.x, a0[t]);  a1[t] = fmaf(m.x, w1v.x, a1[t]);
            a0[t] = fmaf(m.y, w0.y, a0[t]);  a1[t] = fmaf(m.y, w1v.y, a1[t]);
            a0[t] = fmaf(m.z, w0.z, a0[t]);  a1[t] = fmaf(m.z, w1v.z, a1[t]);
            a0[t] = fmaf(m.w, w0.w, a0[t]);  a1[t] = fmaf(m.w, w1v.w, a1[t]);
        }
    }
    __syncwarp();
    #pragma unroll
    for (int t = 0; t < 8; t++) {
        stage[wid][t][lane]      = fmaxf(a0[t], 0.0f);
        stage[wid][t][lane + 32] = fmaxf(a1[t], 0.0f);
    }
    __syncwarp();

    bb0 = b2[lane]; bb1 = b2[lane + 32];
    #pragma unroll
    for (int t = 0; t < 8; t++) { a0[t] = bb0; a1[t] = bb1; }

    #pragma unroll
    for (int k4 = 0; k4 < 16; k4++) {
        float4 w0 = B2q[k4 * 64 + lane];
        float4 w1v = B2q[k4 * 64 + lane + 32];
        #pragma unroll
        for (int t = 0; t < 8; t++) {
            float4 m = *reinterpret_cast<const float4*>(&stage[wid][t][k4 * 4]);
            a0[t] = fmaf(m.x, w0.x, a0[t]);  a1[t] = fmaf(m.x, w1v.x, a1[t]);
            a0[t] = fmaf(m.y, w0.y, a0[t]);  a1[t] = fmaf(m.y, w1v.y, a1[t]);
            a0[t] = fmaf(m.z, w0.z, a0[t]);  a1[t] = fmaf(m.z, w1v.z, a1[t]);
            a0[t] = fmaf(m.w, w0.w, a0[t]);  a1[t] = fmaf(m.w, w1v.w, a1[t]);
        }
    }

    #pragma unroll
    for (int t = 0; t < 8; t++) {
        a0[t] = fmaxf(a0[t], 0.0f);
        a1[t] = fmaxf(a1[t], 0.0f);
        int node = base + t;
        if (node < NN) {
            g_h[node * 64 + lane]      = a0[t];
            g_h[node * 64 + lane + 32] = a1[t];
        }
    }
    __syncthreads();
    #pragma unroll
    for (int t = 0; t < 8; t++) {
        stage[wid][t][lane]      = a0[t];
        stage[wid][t][lane + 32] = a1[t];
    }
    for (int i = tid; i < 1024; i += 128) {
        int k4 = i >> 6, out = i & 63;
        int kb = k4 * 4 * 64 + out;
        B1q[i] = make_float4(dw1[kb]       + dw1[128 * 64 + kb],
                             dw1[kb + 64]  + dw1[128 * 64 + kb + 64],
                             dw1[kb + 128] + dw1[128 * 64 + kb + 128],
                             dw1[kb + 192] + dw1[128 * 64 + kb + 192]);
        B2q[i] = make_float4(dw1[kb]       + dw1[192 * 64 + kb],
                             dw1[kb + 64]  + dw1[192 * 64 + kb + 64],
                             dw1[kb + 128] + dw1[192 * 64 + kb + 128],
                             dw1[kb + 192] + dw1[192 * 64 + kb + 192]);
    }
    __syncthreads();

    float u0[8], u1[8], v0[8], v1[8];
    #pragma unroll
    for (int t = 0; t < 8; t++) { u0[t] = u1[t] = v0[t] = v1[t] = 0.0f; }

    #pragma unroll
    for (int k4 = 0; k4 < 16; k4++) {
        float4 c0 = B1q[k4 * 64 + lane];
        float4 c1 = B1q[k4 * 64 + lane + 32];
        float4 d0 = B2q[k4 * 64 + lane];
        float4 d1 = B2q[k4 * 64 + lane + 32];
        #pragma unroll
        for (int t = 0; t < 8; t++) {
            float4 m = *reinterpret_cast<const float4*>(&stage[wid][t][k4 * 4]);
            u0[t] = fmaf(m.x, c0.x, u0[t]);  u1[t] = fmaf(m.x, c1.x, u1[t]);
            v0[t] = fmaf(m.x, d0.x, v0[t]);  v1[t] = fmaf(m.x, d1.x, v1[t]);
            u0[t] = fmaf(m.y, c0.y, u0[t]);  u1[t] = fmaf(m.y, c1.y, u1[t]);
            v0[t] = fmaf(m.y, d0.y, v0[t]);  v1[t] = fmaf(m.y, d1.y, v1[t]);
            u0[t] = fmaf(m.z, c0.z, u0[t]);  u1[t] = fmaf(m.z, c1.z, u1[t]);
            v0[t] = fmaf(m.z, d0.z, v0[t]);  v1[t] = fmaf(m.z, d1.z, v1[t]);
            u0[t] = fmaf(m.w, c0.w, u0[t]);  u1[t] = fmaf(m.w, c1.w, u1[t]);
            v0[t] = fmaf(m.w, d0.w, v0[t]);  v1[t] = fmaf(m.w, d1.w, v1[t]);
        }
    }
    #pragma unroll
    for (int t = 0; t < 8; t++) {
        int node = base + t;
        if (node < NN) {
            g_u[node * 64 + lane]      = u0[t];
            g_u[node * 64 + lane + 32] = u1[t];
            g_v[node * 64 + lane]      = v0[t];
            g_v[node * 64 + lane + 32] = v1[t];
        }
    }
}

// ===========================================================================
// K3: pair decoder via warp-level bf16 MMA (mma.sync m16n8k16, sm_80+ PTX).
// Hi/lo bf16 split for Prod @ B; UV term enters the fp32 accumulator directly.
// FIX vs R12: staging gathers are row-coalesced (half-warp = one pair row,
// lane&15 = float4 chunk) -> each LDG.128 touches 2 rows / 4 lines instead of
// 16-32 scattered rows.
// ===========================================================================

// byte offsets in dynamic smem
#define OFF_PH  0          // ProdHi bf16 [128][72]  (stride 144B)
#define OFF_PL  18432      // ProdLo bf16 [128][72]
#define OFF_UV  36864      // UV fp32 [128][72]      (stride 288B)
#define OFF_BH  73728      // Bt hi bf16 [64][72]    (Bt[n][k], stride 144B)
#define OFF_BL  82944      // Bt lo bf16 [64][72]
#define OFF_DW2 92160      // dw2 fp32 [64]
#define PAIR_SMEM 92416

__device__ __forceinline__ void split_pack(float fx, float fy, uint32_t& hi, uint32_t& lo) {
    __nv_bfloat16 hx = __float2bfloat16(fx);
    __nv_bfloat16 hy = __float2bfloat16(fy);
    __nv_bfloat16 lx = __float2bfloat16(fx - __bfloat162float(hx));
    __nv_bfloat16 ly = __float2bfloat16(fy - __bfloat162float(hy));
    __nv_bfloat162 h2; h2.x = hx; h2.y = hy;
    __nv_bfloat162 l2; l2.x = lx; l2.y = ly;
    hi = *reinterpret_cast<uint32_t*>(&h2);
    lo = *reinterpret_cast<uint32_t*>(&l2);
}

#define MMA16816(c0, c1, c2, c3, a, b0, b1)                                  \
    asm volatile(                                                            \
        "mma.sync.aligned.m16n8k16.row.col.f32.bf16.bf16.f32 "              \
        "{%0,%1,%2,%3}, {%4,%5,%6,%7}, {%8,%9}, {%0,%1,%2,%3};"             \
        : "+f"(c0), "+f"(c1), "+f"(c2), "+f"(c3)                             \
        : "r"((a)[0]), "r"((a)[1]), "r"((a)[2]), "r"((a)[3]),                \
          "r"(b0), "r"(b1))

__global__ void __launch_bounds__(256) k_pair_mma(
    const int* __restrict__ idx,
    const float* __restrict__ dw1, const float* __restrict__ db1,
    const float* __restrict__ dw2, const float* __restrict__ db2,
    float* __restrict__ out)
{
    extern __shared__ unsigned char sm[];
    int tid = threadIdx.x;
    int wid  = tid >> 5;
    int lane = tid & 31;

    // ---- stage B^T hi/lo: Bt[n][k] = dw1[(64+k)*64 + n] ----
    for (int i = tid; i < 4096; i += 256) {
        int n = i >> 6, k = i & 63;
        float f = dw1[(64 + k) * 64 + n];
        __nv_bfloat16 h = __float2bfloat16(f);
        __nv_bfloat16 l = __float2bfloat16(f - __bfloat162float(h));
        *reinterpret_cast<__nv_bfloat16*>(sm + OFF_BH + n * 144 + k * 2) = h;
        *reinterpret_cast<__nv_bfloat16*>(sm + OFF_BL + n * 144 + k * 2) = l;
    }
    if (tid < 64) reinterpret_cast<float*>(sm + OFF_DW2)[tid] = dw2[tid];

    // ---- stage pairs, row-coalesced: half-warp owns one pair row ----
    {
        int half = lane >> 4;          // 0/1
        int c    = lane & 15;          // float4 chunk (feature 4c..4c+3)
        float4 d4 = reinterpret_cast<const float4*>(db1)[c];
        #pragma unroll
        for (int t = 0; t < 8; t++) {
            int p_local = wid * 16 + t * 2 + half;
            int p = blockIdx.x * 128 + p_local;
            int pc = p < PP ? p : PP - 1;
            int i0 = idx[pc];
            int j0 = idx[PP + pc];
            float4 hi4 = reinterpret_cast<const float4*>(g_h)[i0 * 16 + c];
            float4 hj4 = reinterpret_cast<const float4*>(g_h)[j0 * 16 + c];
            float4 u4  = reinterpret_cast<const float4*>(g_u)[i0 * 16 + c];
            float4 v4  = reinterpret_cast<const float4*>(g_v)[j0 * 16 + c];
            float4 pr = make_float4(hi4.x * hj4.x, hi4.y * hj4.y,
                                    hi4.z * hj4.z, hi4.w * hj4.w);
            float4 uv = make_float4(u4.x + v4.x + d4.x, u4.y + v4.y + d4.y,
                                    u4.z + v4.z + d4.z, u4.w + v4.w + d4.w);
            uint2 ph, pl;
            split_pack(pr.x, pr.y, ph.x, pl.x);
            split_pack(pr.z, pr.w, ph.y, pl.y);
            *reinterpret_cast<uint2*> (sm + OFF_PH + p_local * 144 + c * 8)  = ph;
            *reinterpret_cast<uint2*> (sm + OFF_PL + p_local * 144 + c * 8)  = pl;
            *reinterpret_cast<float4*>(sm + OFF_UV + p_local * 288 + c * 16) = uv;
        }
    }
    __syncthreads();

    int grp  = lane >> 2;    // 0..7
    int tig  = lane & 3;     // 0..3
    int r0   = wid * 16 + grp;

    const uint32_t* PH  = reinterpret_cast<const uint32_t*>(sm + OFF_PH);  // stride 36 u32
    const uint32_t* PL  = reinterpret_cast<const uint32_t*>(sm + OFF_PL);
    const uint32_t* BH  = reinterpret_cast<const uint32_t*>(sm + OFF_BH);
    const uint32_t* BL  = reinterpret_cast<const uint32_t*>(sm + OFF_BL);
    const float*    UVf = reinterpret_cast<const float*>   (sm + OFF_UV);  // stride 72 f32
    const float*   sdw2 = reinterpret_cast<const float*>   (sm + OFF_DW2);

    // hoist A fragments: 4 k-steps, hi and lo
    uint32_t ah[4][4], al[4][4];
    #pragma unroll
    for (int ks = 0; ks < 4; ks++) {
        int k0 = ks * 8 + tig;                 // u32 units
        ah[ks][0] = PH[ r0      * 36 + k0];
        ah[ks][1] = PH[(r0 + 8) * 36 + k0];
        ah[ks][2] = PH[ r0      * 36 + k0 + 4];
        ah[ks][3] = PH[(r0 + 8) * 36 + k0 + 4];
        al[ks][0] = PL[ r0      * 36 + k0];
        al[ks][1] = PL[(r0 + 8) * 36 + k0];
        al[ks][2] = PL[ r0      * 36 + k0 + 4];
        al[ks][3] = PL[(r0 + 8) * 36 + k0 + 4];
    }

    float pa = 0.0f, pb = 0.0f;
    #pragma unroll
    for (int nt = 0; nt < 8; nt++) {
        int n = nt * 8 + grp;
        int cbase = nt * 8 + tig * 2;
        float2 cA = *reinterpret_cast<const float2*>(&UVf[ r0      * 72 + cbase]);
        float2 cB = *reinterpret_cast<const float2*>(&UVf[(r0 + 8) * 72 + cbase]);
        float c0 = cA.x, c1 = cA.y, c2 = cB.x, c3 = cB.y;
        #pragma unroll
        for (int ks = 0; ks < 4; ks++) {
            int kb = ks * 8 + tig;
            uint32_t bh0 = BH[n * 36 + kb], bh1 = BH[n * 36 + kb + 4];
            uint32_t bl0 = BL[n * 36 + kb], bl1 = BL[n * 36 + kb + 4];
            MMA16816(c0, c1, c2, c3, ah[ks], bh0, bh1);   // hi*hi
            MMA16816(c0, c1, c2, c3, ah[ks], bl0, bl1);   // hi*lo
            MMA16816(c0, c1, c2, c3, al[ks], bh0, bh1);   // lo*hi
        }
        float w0 = sdw2[cbase], w1 = sdw2[cbase + 1];
        pa = fmaf(fmaxf(c0, 0.0f), w0, fmaf(fmaxf(c1, 0.0f), w1, pa));
        pb = fmaf(fmaxf(c2, 0.0f), w0, fmaf(fmaxf(c3, 0.0f), w1, pb));
    }

    // reduce across the 4-thread tig group (lanes differ in bits 0,1)
    pa += __shfl_xor_sync(0xffffffffu, pa, 1);
    pa += __shfl_xor_sync(0xffffffffu, pa, 2);
    pb += __shfl_xor_sync(0xffffffffu, pb, 1);
    pb += __shfl_xor_sync(0xffffffffu, pb, 2);

    if (tig == 0) {
        float bo = db2[0];
        int pA = blockIdx.x * 128 + r0;
        int pB = pA + 8;
        if (pA < PP) out[pA] = pa + bo;
        if (pB < PP) out[pB] = pb + bo;
    }
}

// ---------------------------------------------------------------------------
extern "C" void kernel_launch(void* const* d_in, const int* in_sizes, int n_in,
                              void* d_out, int out_size) {
    const float* x   = (const float*)d_in[0];
    const int*   ei  = (const int*)  d_in[1];
    // d_in[2] = curvature (unused by the output)
    const int*   idx = (const int*)  d_in[3];
    const float* w1  = (const float*)d_in[4];
    const float* b1  = (const float*)d_in[5];
    const float* w2  = (const float*)d_in[6];
    const float* b2  = (const float*)d_in[7];
    const float* dw1 = (const float*)d_in[8];
    const float* db1 = (const float*)d_in[9];
    const float* dw2 = (const float*)d_in[10];
    const float* db2 = (const float*)d_in[11];
    float* out = (float*)d_out;

    cudaFuncSetAttribute(k_pair_mma, cudaFuncAttributeMaxDynamicSharedMemorySize,
                         PAIR_SMEM);

    k_init    <<<(NN * 16 + 255) / 256, 256>>>(x);
    k_scatter <<<(EE * 16 + 255) / 256, 256>>>(x, ei);
    k_mlp_uv  <<<(NN + 31) / 32, 128>>>(w1, b1, w2, b2, dw1);
    k_pair_mma<<<(PP + 127) / 128, 256, PAIR_SMEM>>>(idx, dw1, db1, dw2, db2, out);
}

// round 14
// speedup vs baseline: 1.4716x; 1.2330x over previous
#include <cuda_runtime.h>
#include <cuda_bf16.h>
#include <cstdint>

#define NN 100000
#define EE 1600000
#define PP 200000
#define NTILES 782   // ceil(NN/128)

// Scratch (allocation-free rule: __device__ globals)
__device__ float g_h0[NN * 64];   // 2x + scatter_sum
__device__ float g_h [NN * 64];   // node embedding after MLP
__device__ float g_u [NN * 64];   // h @ (A+C)
__device__ float g_v [NN * 64];   // h @ (A+D)

// ---------------------------------------------------------------------------
// K0: h0 = 2*x  (vectorized)
__global__ void k_init(const float* __restrict__ x) {
    int i = blockIdx.x * blockDim.x + threadIdx.x;
    if (i < NN * 16) {
        float4 v = reinterpret_cast<const float4*>(x)[i];
        v.x += v.x; v.y += v.y; v.z += v.z; v.w += v.w;
        reinterpret_cast<float4*>(g_h0)[i] = v;
    }
}

// ---------------------------------------------------------------------------
// K1: scatter  h0[dst] += x[src].  16 lanes per edge (one float4 chunk each).
__global__ void __launch_bounds__(256) k_scatter(const float* __restrict__ x,
                                                 const int* __restrict__ ei) {
    int u = blockIdx.x * blockDim.x + threadIdx.x;
    if (u >= EE * 16) return;
    int e = u >> 4;
    int c = u & 15;
    int src = ei[e];
    int dst = ei[EE + e];
    float4 val = reinterpret_cast<const float4*>(x)[src * 16 + c];
    float* p = &g_h0[dst * 64 + c * 4];
    asm volatile("red.global.add.v4.f32 [%0], {%1, %2, %3, %4};"
                 :: "l"(p), "f"(val.x), "f"(val.y), "f"(val.z), "f"(val.w)
                 : "memory");
}

// ---------------------------------------------------------------------------
// shared MMA helpers
__device__ __forceinline__ void split_pack(float fx, float fy, uint32_t& hi, uint32_t& lo) {
    __nv_bfloat16 hx = __float2bfloat16(fx);
    __nv_bfloat16 hy = __float2bfloat16(fy);
    __nv_bfloat16 lx = __float2bfloat16(fx - __bfloat162float(hx));
    __nv_bfloat16 ly = __float2bfloat16(fy - __bfloat162float(hy));
    __nv_bfloat162 h2; h2.x = hx; h2.y = hy;
    __nv_bfloat162 l2; l2.x = lx; l2.y = ly;
    hi = *reinterpret_cast<uint32_t*>(&h2);
    lo = *reinterpret_cast<uint32_t*>(&l2);
}

__device__ __forceinline__ void split_sts(unsigned char* sm, int offH, int offL,
                                          int byte_off, float f) {
    __nv_bfloat16 h = __float2bfloat16(f);
    __nv_bfloat16 l = __float2bfloat16(f - __bfloat162float(h));
    *reinterpret_cast<__nv_bfloat16*>(sm + offH + byte_off) = h;
    *reinterpret_cast<__nv_bfloat16*>(sm + offL + byte_off) = l;
}

#define MMA16816(c0, c1, c2, c3, a, b0, b1)                                  \
    asm volatile(                                                            \
        "mma.sync.aligned.m16n8k16.row.col.f32.bf16.bf16.f32 "              \
        "{%0,%1,%2,%3}, {%4,%5,%6,%7}, {%8,%9}, {%0,%1,%2,%3};"             \
        : "+f"(c0), "+f"(c1), "+f"(c2), "+f"(c3)                             \
        : "r"((a)[0]), "r"((a)[1]), "r"((a)[2]), "r"((a)[3]),                \
          "r"(b0), "r"(b1))

// ===========================================================================
// K2 (NEW): node chain h0 -> L1 -> relu -> L2 -> relu -> {u,v} fully on
// warp-level bf16 MMA with hi/lo split. D-fragment of one GEMM is repacked in
// registers into the A-fragment of the next (no smem between layers).
// Persistent CTAs: weights staged once; each warp stages only its own 16
// A-rows -> no block syncs inside the tile loop.
// ===========================================================================

// smem byte offsets; weight tiles Bt[n][k] bf16, stride 144B (72 bf16/row)
#define MOFF_W1H 0
#define MOFF_W1L 9216
#define MOFF_W2H 18432
#define MOFF_W2L 27648
#define MOFF_ACH 36864
#define MOFF_ACL 46080
#define MOFF_ADH 55296
#define MOFF_ADL 64512
#define MOFF_A   73728      // per-warp 4608B: hi [16][72] 2304B + lo 2304B
#define MOFF_B1  110592     // b1 fp32 [64]
#define MOFF_B2  110848     // b2 fp32 [64]
#define MLP_SMEM 111104

// one GEMM layer on hoisted A fragments, weights from smem
#define MMA_LAYER(D, WH, WL)                                                 \
    _Pragma("unroll")                                                        \
    for (int nt = 0; nt < 8; nt++) {                                         \
        int n = nt * 8 + grp;                                                \
        _Pragma("unroll")                                                    \
        for (int ks = 0; ks < 4; ks++) {                                     \
            int kb = ks * 8 + tig;                                           \
            uint32_t bh0 = (WH)[n * 36 + kb], bh1 = (WH)[n * 36 + kb + 4];   \
            uint32_t bl0 = (WL)[n * 36 + kb], bl1 = (WL)[n * 36 + kb + 4];   \
            MMA16816(D[nt].x, D[nt].y, D[nt].z, D[nt].w, ah[ks], bh0, bh1);  \
            MMA16816(D[nt].x, D[nt].y, D[nt].z, D[nt].w, ah[ks], bl0, bl1);  \
            MMA16816(D[nt].x, D[nt].y, D[nt].z, D[nt].w, al[ks], bh0, bh1);  \
        }                                                                    \
    }

// repack relu'd D into next-layer A fragments (pure register ops)
#define REPACK_FRAGS(D)                                                      \
    _Pragma("unroll")                                                        \
    for (int ks = 0; ks < 4; ks++) {                                         \
        split_pack(D[2*ks].x,   D[2*ks].y,   ah[ks][0], al[ks][0]);          \
        split_pack(D[2*ks].z,   D[2*ks].w,   ah[ks][1], al[ks][1]);          \
        split_pack(D[2*ks+1].x, D[2*ks+1].y, ah[ks][2], al[ks][2]);          \
        split_pack(D[2*ks+1].z, D[2*ks+1].w, ah[ks][3], al[ks][3]);          \
    }

#define STORE_ROWS(dst, D)                                                   \
    _Pragma("unroll")                                                        \
    for (int nt = 0; nt < 8; nt++) {                                         \
        int cbase = nt * 8 + tig * 2;                                        \
        if (nodeA < NN)                                                      \
            *reinterpret_cast<float2*>(&dst[nodeA * 64 + cbase]) =           \
                make_float2(D[nt].x, D[nt].y);                               \
        if (nodeB < NN)                                                      \
            *reinterpret_cast<float2*>(&dst[nodeB * 64 + cbase]) =           \
                make_float2(D[nt].z, D[nt].w);                               \
    }

__global__ void __launch_bounds__(256) k_mlp_uv_mma(
    const float* __restrict__ w1, const float* __restrict__ b1,
    const float* __restrict__ w2, const float* __restrict__ b2,
    const float* __restrict__ dw1)
{
    extern __shared__ unsigned char sm[];
    int tid  = threadIdx.x;
    int wid  = tid >> 5;
    int lane = tid & 31;

    // ---- stage all weight matrices (once per CTA), Bt[n][k] hi/lo ----
    for (int i = tid; i < 4096; i += 256) {
        int n = i & 63, k = i >> 6;          // coalesced over n
        int bo = n * 144 + k * 2;
        float fa = dw1[k * 64 + n];
        split_sts(sm, MOFF_W1H, MOFF_W1L, bo, w1[k * 64 + n]);
        split_sts(sm, MOFF_W2H, MOFF_W2L, bo, w2[k * 64 + n]);
        split_sts(sm, MOFF_ACH, MOFF_ACL, bo, fa + dw1[(128 + k) * 64 + n]);
        split_sts(sm, MOFF_ADH, MOFF_ADL, bo, fa + dw1[(192 + k) * 64 + n]);
    }
    if (tid < 64) {
        reinterpret_cast<float*>(sm + MOFF_B1)[tid] = b1[tid];
        reinterpret_cast<float*>(sm + MOFF_B2)[tid] = b2[tid];
    }
    __syncthreads();

    const uint32_t* W1H = reinterpret_cast<const uint32_t*>(sm + MOFF_W1H);
    const uint32_t* W1L = reinterpret_cast<const uint32_t*>(sm + MOFF_W1L);
    const uint32_t* W2H = reinterpret_cast<const uint32_t*>(sm + MOFF_W2H);
    const uint32_t* W2L = reinterpret_cast<const uint32_t*>(sm + MOFF_W2L);
    const uint32_t* ACH = reinterpret_cast<const uint32_t*>(sm + MOFF_ACH);
    const uint32_t* ACL = reinterpret_cast<const uint32_t*>(sm + MOFF_ACL);
    const uint32_t* ADH = reinterpret_cast<const uint32_t*>(sm + MOFF_ADH);
    const uint32_t* ADL = reinterpret_cast<const uint32_t*>(sm + MOFF_ADL);
    const float* sb1 = reinterpret_cast<const float*>(sm + MOFF_B1);
    const float* sb2 = reinterpret_cast<const float*>(sm + MOFF_B2);

    unsigned char* Awarp = sm + MOFF_A + wid * 4608;
    const uint32_t* AH = reinterpret_cast<const uint32_t*>(Awarp);
    const uint32_t* AL = reinterpret_cast<const uint32_t*>(Awarp + 2304);

    int grp = lane >> 2;
    int tig = lane & 3;
    int half = lane >> 4;       // staging role
    int c    = lane & 15;

    for (int tile = blockIdx.x; tile < NTILES; tile += gridDim.x) {
        // ---- stage this warp's 16 A-rows (h0), hi/lo, row-coalesced ----
        #pragma unroll
        for (int t = 0; t < 8; t++) {
            int rw = t * 2 + half;                       // row in warp 0..15
            int node = tile * 128 + wid * 16 + rw;
            int nc = node < NN ? node : NN - 1;
            float4 v = reinterpret_cast<const float4*>(g_h0)[nc * 16 + c];
            uint32_t h0, l0, h1, l1;
            split_pack(v.x, v.y, h0, l0);
            split_pack(v.z, v.w, h1, l1);
            *reinterpret_cast<uint2*>(Awarp + rw * 144 + c * 8)        = make_uint2(h0, h1);
            *reinterpret_cast<uint2*>(Awarp + 2304 + rw * 144 + c * 8) = make_uint2(l0, l1);
        }
        __syncwarp();

        // ---- hoist A fragments ----
        uint32_t ah[4][4], al[4][4];
        #pragma unroll
        for (int ks = 0; ks < 4; ks++) {
            int k0 = ks * 8 + tig;
            ah[ks][0] = AH[ grp      * 36 + k0];
            ah[ks][1] = AH[(grp + 8) * 36 + k0];
            ah[ks][2] = AH[ grp      * 36 + k0 + 4];
            ah[ks][3] = AH[(grp + 8) * 36 + k0 + 4];
            al[ks][0] = AL[ grp      * 36 + k0];
            al[ks][1] = AL[(grp + 8) * 36 + k0];
            al[ks][2] = AL[ grp      * 36 + k0 + 4];
            al[ks][3] = AL[(grp + 8) * 36 + k0 + 4];
        }

        int nodeA = tile * 128 + wid * 16 + grp;
        int nodeB = nodeA + 8;
        float4 D[8];

        // ---- layer 1: D = A @ w1 + b1, relu ----
        #pragma unroll
        for (int nt = 0; nt < 8; nt++) {
            int cbase = nt * 8 + tig * 2;
            float bx = sb1[cbase], by = sb1[cbase + 1];
            D[nt] = make_float4(bx, by, bx, by);
        }
        MMA_LAYER(D, W1H, W1L)
        #pragma unroll
        for (int nt = 0; nt < 8; nt++) {
            D[nt].x = fmaxf(D[nt].x, 0.0f); D[nt].y = fmaxf(D[nt].y, 0.0f);
            D[nt].z = fmaxf(D[nt].z, 0.0f); D[nt].w = fmaxf(D[nt].w, 0.0f);
        }
        REPACK_FRAGS(D)

        // ---- layer 2: D = A @ w2 + b2, relu (outer) ----
        #pragma unroll
        for (int nt = 0; nt < 8; nt++) {
            int cbase = nt * 8 + tig * 2;
            float bx = sb2[cbase], by = sb2[cbase + 1];
            D[nt] = make_float4(bx, by, bx, by);
        }
        MMA_LAYER(D, W2H, W2L)
        #pragma unroll
        for (int nt = 0; nt < 8; nt++) {
            D[nt].x = fmaxf(D[nt].x, 0.0f); D[nt].y = fmaxf(D[nt].y, 0.0f);
            D[nt].z = fmaxf(D[nt].z, 0.0f); D[nt].w = fmaxf(D[nt].w, 0.0f);
        }
        STORE_ROWS(g_h, D)
        REPACK_FRAGS(D)

        // ---- u = h @ (A+C) ----
        #pragma unroll
        for (int nt = 0; nt < 8; nt++) D[nt] = make_float4(0.f, 0.f, 0.f, 0.f);
        MMA_LAYER(D, ACH, ACL)
        STORE_ROWS(g_u, D)

        // ---- v = h @ (A+D) ----
        #pragma unroll
        for (int nt = 0; nt < 8; nt++) D[nt] = make_float4(0.f, 0.f, 0.f, 0.f);
        MMA_LAYER(D, ADH, ADL)
        STORE_ROWS(g_v, D)
    }
}

// ===========================================================================
// K3: pair decoder via warp-level bf16 MMA (unchanged from R13).
// ===========================================================================

#define OFF_PH  0
#define OFF_PL  18432
#define OFF_UV  36864
#define OFF_BH  73728
#define OFF_BL  82944
#define OFF_DW2 92160
#define PAIR_SMEM 92416

__global__ void __launch_bounds__(256) k_pair_mma(
    const int* __restrict__ idx,
    const float* __restrict__ dw1, const float* __restrict__ db1,
    const float* __restrict__ dw2, const float* __restrict__ db2,
    float* __restrict__ out)
{
    extern __shared__ unsigned char sm[];
    int tid = threadIdx.x;
    int wid  = tid >> 5;
    int lane = tid & 31;

    for (int i = tid; i < 4096; i += 256) {
        int n = i >> 6, k = i & 63;
        float f = dw1[(64 + k) * 64 + n];
        __nv_bfloat16 h = __float2bfloat16(f);
        __nv_bfloat16 l = __float2bfloat16(f - __bfloat162float(h));
        *reinterpret_cast<__nv_bfloat16*>(sm + OFF_BH + n * 144 + k * 2) = h;
        *reinterpret_cast<__nv_bfloat16*>(sm + OFF_BL + n * 144 + k * 2) = l;
    }
    if (tid < 64) reinterpret_cast<float*>(sm + OFF_DW2)[tid] = dw2[tid];

    {
        int half = lane >> 4;
        int c    = lane & 15;
        float4 d4 = reinterpret_cast<const float4*>(db1)[c];
        #pragma unroll
        for (int t = 0; t < 8; t++) {
            int p_local = wid * 16 + t * 2 + half;
            int p = blockIdx.x * 128 + p_local;
            int pc = p < PP ? p : PP - 1;
            int i0 = idx[pc];
            int j0 = idx[PP + pc];
            float4 hi4 = reinterpret_cast<const float4*>(g_h)[i0 * 16 + c];
            float4 hj4 = reinterpret_cast<const float4*>(g_h)[j0 * 16 + c];
            float4 u4  = reinterpret_cast<const float4*>(g_u)[i0 * 16 + c];
            float4 v4  = reinterpret_cast<const float4*>(g_v)[j0 * 16 + c];
            float4 pr = make_float4(hi4.x * hj4.x, hi4.y * hj4.y,
                                    hi4.z * hj4.z, hi4.w * hj4.w);
            float4 uv = make_float4(u4.x + v4.x + d4.x, u4.y + v4.y + d4.y,
                                    u4.z + v4.z + d4.z, u4.w + v4.w + d4.w);
            uint2 ph, pl;
            split_pack(pr.x, pr.y, ph.x, pl.x);
            split_pack(pr.z, pr.w, ph.y, pl.y);
            *reinterpret_cast<uint2*> (sm + OFF_PH + p_local * 144 + c * 8)  = ph;
            *reinterpret_cast<uint2*> (sm + OFF_PL + p_local * 144 + c * 8)  = pl;
            *reinterpret_cast<float4*>(sm + OFF_UV + p_local * 288 + c * 16) = uv;
        }
    }
    __syncthreads();

    int grp  = lane >> 2;
    int tig  = lane & 3;
    int r0   = wid * 16 + grp;

    const uint32_t* PH  = reinterpret_cast<const uint32_t*>(sm + OFF_PH);
    const uint32_t* PL  = reinterpret_cast<const uint32_t*>(sm + OFF_PL);
    const uint32_t* BH  = reinterpret_cast<const uint32_t*>(sm + OFF_BH);
    const uint32_t* BL  = reinterpret_cast<const uint32_t*>(sm + OFF_BL);
    const float*    UVf = reinterpret_cast<const float*>   (sm + OFF_UV);
    const float*   sdw2 = reinterpret_cast<const float*>   (sm + OFF_DW2);

    uint32_t ah[4][4], al[4][4];
    #pragma unroll
    for (int ks = 0; ks < 4; ks++) {
        int k0 = ks * 8 + tig;
        ah[ks][0] = PH[ r0      * 36 + k0];
        ah[ks][1] = PH[(r0 + 8) * 36 + k0];
        ah[ks][2] = PH[ r0      * 36 + k0 + 4];
        ah[ks][3] = PH[(r0 + 8) * 36 + k0 + 4];
        al[ks][0] = PL[ r0      * 36 + k0];
        al[ks][1] = PL[(r0 + 8) * 36 + k0];
        al[ks][2] = PL[ r0      * 36 + k0 + 4];
        al[ks][3] = PL[(r0 + 8) * 36 + k0 + 4];
    }

    float pa = 0.0f, pb = 0.0f;
    #pragma unroll
    for (int nt = 0; nt < 8; nt++) {
        int n = nt * 8 + grp;
        int cbase = nt * 8 + tig * 2;
        float2 cA = *reinterpret_cast<const float2*>(&UVf[ r0      * 72 + cbase]);
        float2 cB = *reinterpret_cast<const float2*>(&UVf[(r0 + 8) * 72 + cbase]);
        float c0 = cA.x, c1 = cA.y, c2 = cB.x, c3 = cB.y;
        #pragma unroll
        for (int ks = 0; ks < 4; ks++) {
            int kb = ks * 8 + tig;
            uint32_t bh0 = BH[n * 36 + kb], bh1 = BH[n * 36 + kb + 4];
            uint32_t bl0 = BL[n * 36 + kb], bl1 = BL[n * 36 + kb + 4];
            MMA16816(c0, c1, c2, c3, ah[ks], bh0, bh1);
            MMA16816(c0, c1, c2, c3, ah[ks], bl0, bl1);
            MMA16816(c0, c1, c2, c3, al[ks], bh0, bh1);
        }
        float w0 = sdw2[cbase], w1 = sdw2[cbase + 1];
        pa = fmaf(fmaxf(c0, 0.0f), w0, fmaf(fmaxf(c1, 0.0f), w1, pa));
        pb = fmaf(fmaxf(c2, 0.0f), w0, fmaf(fmaxf(c3, 0.0f), w1, pb));
    }

    pa += __shfl_xor_sync(0xffffffffu, pa, 1);
    pa += __shfl_xor_sync(0xffffffffu, pa, 2);
    pb += __shfl_xor_sync(0xffffffffu, pb, 1);
    pb += __shfl_xor_sync(0xffffffffu, pb, 2);

    if (tig == 0) {
        float bo = db2[0];
        int pA = blockIdx.x * 128 + r0;
        int pB = pA + 8;
        if (pA < PP) out[pA] = pa + bo;
        if (pB < PP) out[pB] = pb + bo;
    }
}

// ---------------------------------------------------------------------------
extern "C" void kernel_launch(void* const* d_in, const int* in_sizes, int n_in,
                              void* d_out, int out_size) {
    const float* x   = (const float*)d_in[0];
    const int*   ei  = (const int*)  d_in[1];
    // d_in[2] = curvature (unused by the output)
    const int*   idx = (const int*)  d_in[3];
    const float* w1  = (const float*)d_in[4];
    const float* b1  = (const float*)d_in[5];
    const float* w2  = (const float*)d_in[6];
    const float* b2  = (const float*)d_in[7];
    const float* dw1 = (const float*)d_in[8];
    const float* db1 = (const float*)d_in[9];
    const float* dw2 = (const float*)d_in[10];
    const float* db2 = (const float*)d_in[11];
    float* out = (float*)d_out;

    cudaFuncSetAttribute(k_mlp_uv_mma, cudaFuncAttributeMaxDynamicSharedMemorySize,
                         MLP_SMEM);
    cudaFuncSetAttribute(k_pair_mma, cudaFuncAttributeMaxDynamicSharedMemorySize,
                         PAIR_SMEM);

    k_init      <<<(NN * 16 + 255) / 256, 256>>>(x);
    k_scatter   <<<(EE * 16 + 255) / 256, 256>>>(x, ei);
    k_mlp_uv_mma<<<296, 256, MLP_SMEM>>>(w1, b1, w2, b2, dw1);
    k_pair_mma  <<<(PP + 127) / 128, 256, PAIR_SMEM>>>(idx, dw1, db1, dw2, db2, out);
}

// round 15
// speedup vs baseline: 1.6290x; 1.1070x over previous
#include <cuda_runtime.h>
#include <cuda_bf16.h>
#include <cstdint>

#define NN 100000
#define EE 1600000
#define PP 200000
#define NTILES 782   // ceil(NN/128)
#define NB 98        // ceil(NN/1024) scan blocks

// Scratch (allocation-free rule: __device__ globals)
__device__ float g_h0[NN * 64];   // 2x + gather_sum
__device__ float g_h [NN * 64];   // node embedding after MLP
__device__ float g_u [NN * 64];   // h @ (A+C)
__device__ float g_v [NN * 64];   // h @ (A+D)
// CSR scratch
__device__ int g_deg[NN + 1];
__device__ int g_cur[NN + 1];
__device__ int g_off[NN + 1];
__device__ int g_adj[EE];
__device__ int g_blksum[NB];
__device__ int g_blkoff[NB];

// ---------------------------------------------------------------------------
// CSR build: zero -> count -> scan(3) -> fill
__global__ void k_zero() {
    int i = blockIdx.x * blockDim.x + threadIdx.x;
    if (i <= NN) { g_deg[i] = 0; g_cur[i] = 0; }
}

__global__ void __launch_bounds__(256) k_count(const int* __restrict__ ei) {
    int e = blockIdx.x * blockDim.x + threadIdx.x;
    if (e < EE) atomicAdd(&g_deg[ei[EE + e]], 1);
}

__global__ void __launch_bounds__(1024) k_scan1() {
    __shared__ int s[1024];
    int t = threadIdx.x;
    int i = blockIdx.x * 1024 + t;
    int v = (i < NN) ? g_deg[i] : 0;
    s[t] = v;
    __syncthreads();
    #pragma unroll
    for (int o = 1; o < 1024; o <<= 1) {
        int tv = (t >= o) ? s[t - o] : 0;
        __syncthreads();
        s[t] += tv;
        __syncthreads();
    }
    if (i < NN) g_off[i] = s[t] - v;          // block-local exclusive
    if (t == 1023) g_blksum[blockIdx.x] = s[t];
}

__global__ void k_scan2() {
    if (threadIdx.x == 0) {
        int run = 0;
        for (int b = 0; b < NB; b++) { g_blkoff[b] = run; run += g_blksum[b]; }
    }
}

__global__ void k_scan3() {
    int i = blockIdx.x * blockDim.x + threadIdx.x;
    if (i < NN) g_off[i] += g_blkoff[i >> 10];
    if (i == 0) g_off[NN] = EE;
}

__global__ void __launch_bounds__(256) k_fill(const int* __restrict__ ei) {
    int e = blockIdx.x * blockDim.x + threadIdx.x;
    if (e >= EE) return;
    int src = ei[e];
    int dst = ei[EE + e];
    int pos = atomicAdd(&g_cur[dst], 1);
    g_adj[g_off[dst] + pos] = src;
}

// ---------------------------------------------------------------------------
// K1: aggregation as gather: h0[n] = 2*x[n] + sum_{s in adj(n)} x[s]
// Half-warp per node; lane c owns float4 chunk c. adj batched 16-wide and
// broadcast via shfl within the half-warp.
__global__ void __launch_bounds__(256) k_agg(const float* __restrict__ x) {
    int hw = blockIdx.x * 16 + (threadIdx.x >> 4);
    int c  = threadIdx.x & 15;
    if (hw >= NN) return;
    unsigned hm = 0xFFFFu << (threadIdx.x & 16);

    const float4* x4 = reinterpret_cast<const float4*>(x);
    float4 acc = x4[hw * 16 + c];
    acc.x += acc.x; acc.y += acc.y; acc.z += acc.z; acc.w += acc.w;

    int off0 = g_off[hw];
    int off1 = g_off[hw + 1];
    for (int base = off0; base < off1; base += 16) {
        int idxv = (base + c < off1) ? g_adj[base + c] : 0;
        int cnt  = off1 - base; if (cnt > 16) cnt = 16;
        #pragma unroll 4
        for (int t = 0; t < cnt; t++) {
            int s = __shfl_sync(hm, idxv, t, 16);
            float4 v = x4[s * 16 + c];
            acc.x += v.x; acc.y += v.y; acc.z += v.z; acc.w += v.w;
        }
    }
    reinterpret_cast<float4*>(g_h0)[hw * 16 + c] = acc;
}

// ---------------------------------------------------------------------------
// shared MMA helpers
__device__ __forceinline__ void split_pack(float fx, float fy, uint32_t& hi, uint32_t& lo) {
    __nv_bfloat16 hx = __float2bfloat16(fx);
    __nv_bfloat16 hy = __float2bfloat16(fy);
    __nv_bfloat16 lx = __float2bfloat16(fx - __bfloat162float(hx));
    __nv_bfloat16 ly = __float2bfloat16(fy - __bfloat162float(hy));
    __nv_bfloat162 h2; h2.x = hx; h2.y = hy;
    __nv_bfloat162 l2; l2.x = lx; l2.y = ly;
    hi = *reinterpret_cast<uint32_t*>(&h2);
    lo = *reinterpret_cast<uint32_t*>(&l2);
}

__device__ __forceinline__ void split_sts(unsigned char* sm, int offH, int offL,
                                          int byte_off, float f) {
    __nv_bfloat16 h = __float2bfloat16(f);
    __nv_bfloat16 l = __float2bfloat16(f - __bfloat162float(h));
    *reinterpret_cast<__nv_bfloat16*>(sm + offH + byte_off) = h;
    *reinterpret_cast<__nv_bfloat16*>(sm + offL + byte_off) = l;
}

#define MMA16816(c0, c1, c2, c3, a, b0, b1)                                  \
    asm volatile(                                                            \
        "mma.sync.aligned.m16n8k16.row.col.f32.bf16.bf16.f32 "              \
        "{%0,%1,%2,%3}, {%4,%5,%6,%7}, {%8,%9}, {%0,%1,%2,%3};"             \
        : "+f"(c0), "+f"(c1), "+f"(c2), "+f"(c3)                             \
        : "r"((a)[0]), "r"((a)[1]), "r"((a)[2]), "r"((a)[3]),                \
          "r"(b0), "r"(b1))

// ===========================================================================
// K2: node chain on warp-level bf16 MMA (unchanged from R14).
// ===========================================================================

#define MOFF_W1H 0
#define MOFF_W1L 9216
#define MOFF_W2H 18432
#define MOFF_W2L 27648
#define MOFF_ACH 36864
#define MOFF_ACL 46080
#define MOFF_ADH 55296
#define MOFF_ADL 64512
#define MOFF_A   73728
#define MOFF_B1  110592
#define MOFF_B2  110848
#define MLP_SMEM 111104

#define MMA_LAYER(D, WH, WL)                                                 \
    _Pragma("unroll")                                                        \
    for (int nt = 0; nt < 8; nt++) {                                         \
        int n = nt * 8 + grp;                                                \
        _Pragma("unroll")                                                    \
        for (int ks = 0; ks < 4; ks++) {                                     \
            int kb = ks * 8 + tig;                                           \
            uint32_t bh0 = (WH)[n * 36 + kb], bh1 = (WH)[n * 36 + kb + 4];   \
            uint32_t bl0 = (WL)[n * 36 + kb], bl1 = (WL)[n * 36 + kb + 4];   \
            MMA16816(D[nt].x, D[nt].y, D[nt].z, D[nt].w, ah[ks], bh0, bh1);  \
            MMA16816(D[nt].x, D[nt].y, D[nt].z, D[nt].w, ah[ks], bl0, bl1);  \
            MMA16816(D[nt].x, D[nt].y, D[nt].z, D[nt].w, al[ks], bh0, bh1);  \
        }                                                                    \
    }

#define REPACK_FRAGS(D)                                                      \
    _Pragma("unroll")                                                        \
    for (int ks = 0; ks < 4; ks++) {                                         \
        split_pack(D[2*ks].x,   D[2*ks].y,   ah[ks][0], al[ks][0]);          \
        split_pack(D[2*ks].z,   D[2*ks].w,   ah[ks][1], al[ks][1]);          \
        split_pack(D[2*ks+1].x, D[2*ks+1].y, ah[ks][2], al[ks][2]);          \
        split_pack(D[2*ks+1].z, D[2*ks+1].w, ah[ks][3], al[ks][3]);          \
    }

#define STORE_ROWS(dst, D)                                                   \
    _Pragma("unroll")                                                        \
    for (int nt = 0; nt < 8; nt++) {                                         \
        int cbase = nt * 8 + tig * 2;                                        \
        if (nodeA < NN)                                                      \
            *reinterpret_cast<float2*>(&dst[nodeA * 64 + cbase]) =           \
                make_float2(D[nt].x, D[nt].y);                               \
        if (nodeB < NN)                                                      \
            *reinterpret_cast<float2*>(&dst[nodeB * 64 + cbase]) =           \
                make_float2(D[nt].z, D[nt].w);                               \
    }

__global__ void __launch_bounds__(256) k_mlp_uv_mma(
    const float* __restrict__ w1, const float* __restrict__ b1,
    const float* __restrict__ w2, const float* __restrict__ b2,
    const float* __restrict__ dw1)
{
    extern __shared__ unsigned char sm[];
    int tid  = threadIdx.x;
    int wid  = tid >> 5;
    int lane = tid & 31;

    for (int i = tid; i < 4096; i += 256) {
        int n = i & 63, k = i >> 6;
        int bo = n * 144 + k * 2;
        float fa = dw1[k * 64 + n];
        split_sts(sm, MOFF_W1H, MOFF_W1L, bo, w1[k * 64 + n]);
        split_sts(sm, MOFF_W2H, MOFF_W2L, bo, w2[k * 64 + n]);
        split_sts(sm, MOFF_ACH, MOFF_ACL, bo, fa + dw1[(128 + k) * 64 + n]);
        split_sts(sm, MOFF_ADH, MOFF_ADL, bo, fa + dw1[(192 + k) * 64 + n]);
    }
    if (tid < 64) {
        reinterpret_cast<float*>(sm + MOFF_B1)[tid] = b1[tid];
        reinterpret_cast<float*>(sm + MOFF_B2)[tid] = b2[tid];
    }
    __syncthreads();

    const uint32_t* W1H = reinterpret_cast<const uint32_t*>(sm + MOFF_W1H);
    const uint32_t* W1L = reinterpret_cast<const uint32_t*>(sm + MOFF_W1L);
    const uint32_t* W2H = reinterpret_cast<const uint32_t*>(sm + MOFF_W2H);
    const uint32_t* W2L = reinterpret_cast<const uint32_t*>(sm + MOFF_W2L);
    const uint32_t* ACH = reinterpret_cast<const uint32_t*>(sm + MOFF_ACH);
    const uint32_t* ACL = reinterpret_cast<const uint32_t*>(sm + MOFF_ACL);
    const uint32_t* ADH = reinterpret_cast<const uint32_t*>(sm + MOFF_ADH);
    const uint32_t* ADL = reinterpret_cast<const uint32_t*>(sm + MOFF_ADL);
    const float* sb1 = reinterpret_cast<const float*>(sm + MOFF_B1);
    const float* sb2 = reinterpret_cast<const float*>(sm + MOFF_B2);

    unsigned char* Awarp = sm + MOFF_A + wid * 4608;
    const uint32_t* AH = reinterpret_cast<const uint32_t*>(Awarp);
    const uint32_t* AL = reinterpret_cast<const uint32_t*>(Awarp + 2304);

    int grp = lane >> 2;
    int tig = lane & 3;
    int half = lane >> 4;
    int c    = lane & 15;

    for (int tile = blockIdx.x; tile < NTILES; tile += gridDim.x) {
        #pragma unroll
        for (int t = 0; t < 8; t++) {
            int rw = t * 2 + half;
            int node = tile * 128 + wid * 16 + rw;
            int nc = node < NN ? node : NN - 1;
            float4 v = reinterpret_cast<const float4*>(g_h0)[nc * 16 + c];
            uint32_t h0, l0, h1, l1;
            split_pack(v.x, v.y, h0, l0);
            split_pack(v.z, v.w, h1, l1);
            *reinterpret_cast<uint2*>(Awarp + rw * 144 + c * 8)        = make_uint2(h0, h1);
            *reinterpret_cast<uint2*>(Awarp + 2304 + rw * 144 + c * 8) = make_uint2(l0, l1);
        }
        __syncwarp();

        uint32_t ah[4][4], al[4][4];
        #pragma unroll
        for (int ks = 0; ks < 4; ks++) {
            int k0 = ks * 8 + tig;
            ah[ks][0] = AH[ grp      * 36 + k0];
            ah[ks][1] = AH[(grp + 8) * 36 + k0];
            ah[ks][2] = AH[ grp      * 36 + k0 + 4];
            ah[ks][3] = AH[(grp + 8) * 36 + k0 + 4];
            al[ks][0] = AL[ grp      * 36 + k0];
            al[ks][1] = AL[(grp + 8) * 36 + k0];
            al[ks][2] = AL[ grp      * 36 + k0 + 4];
            al[ks][3] = AL[(grp + 8) * 36 + k0 + 4];
        }

        int nodeA = tile * 128 + wid * 16 + grp;
        int nodeB = nodeA + 8;
        float4 D[8];

        #pragma unroll
        for (int nt = 0; nt < 8; nt++) {
            int cbase = nt * 8 + tig * 2;
            float bx = sb1[cbase], by = sb1[cbase + 1];
            D[nt] = make_float4(bx, by, bx, by);
        }
        MMA_LAYER(D, W1H, W1L)
        #pragma unroll
        for (int nt = 0; nt < 8; nt++) {
            D[nt].x = fmaxf(D[nt].x, 0.0f); D[nt].y = fmaxf(D[nt].y, 0.0f);
            D[nt].z = fmaxf(D[nt].z, 0.0f); D[nt].w = fmaxf(D[nt].w, 0.0f);
        }
        REPACK_FRAGS(D)

        #pragma unroll
        for (int nt = 0; nt < 8; nt++) {
            int cbase = nt * 8 + tig * 2;
            float bx = sb2[cbase], by = sb2[cbase + 1];
            D[nt] = make_float4(bx, by, bx, by);
        }
        MMA_LAYER(D, W2H, W2L)
        #pragma unroll
        for (int nt = 0; nt < 8; nt++) {
            D[nt].x = fmaxf(D[nt].x, 0.0f); D[nt].y = fmaxf(D[nt].y, 0.0f);
            D[nt].z = fmaxf(D[nt].z, 0.0f); D[nt].w = fmaxf(D[nt].w, 0.0f);
        }
        STORE_ROWS(g_h, D)
        REPACK_FRAGS(D)

        #pragma unroll
        for (int nt = 0; nt < 8; nt++) D[nt] = make_float4(0.f, 0.f, 0.f, 0.f);
        MMA_LAYER(D, ACH, ACL)
        STORE_ROWS(g_u, D)

        #pragma unroll
        for (int nt = 0; nt < 8; nt++) D[nt] = make_float4(0.f, 0.f, 0.f, 0.f);
        MMA_LAYER(D, ADH, ADL)
        STORE_ROWS(g_v, D)
    }
}

// ===========================================================================
// K3: pair decoder. Change vs R14: UV tile is NOT staged in smem — the fp32
// C-fragment init loads u/v directly from global (float2 per fragment slot).
// smem 92KB -> 55.8KB => 2x occupancy.
// ===========================================================================

#define OFF_PH  0
#define OFF_PL  18432
#define OFF_BH  36864
#define OFF_BL  46080
#define OFF_DW2 55296
#define OFF_DB1 55552
#define PAIR_SMEM 55808

__global__ void __launch_bounds__(256) k_pair_mma(
    const int* __restrict__ idx,
    const float* __restrict__ dw1, const float* __restrict__ db1,
    const float* __restrict__ dw2, const float* __restrict__ db2,
    float* __restrict__ out)
{
    extern __shared__ unsigned char sm[];
    int tid = threadIdx.x;
    int wid  = tid >> 5;
    int lane = tid & 31;

    for (int i = tid; i < 4096; i += 256) {
        int n = i >> 6, k = i & 63;
        float f = dw1[(64 + k) * 64 + n];
        __nv_bfloat16 h = __float2bfloat16(f);
        __nv_bfloat16 l = __float2bfloat16(f - __bfloat162float(h));
        *reinterpret_cast<__nv_bfloat16*>(sm + OFF_BH + n * 144 + k * 2) = h;
        *reinterpret_cast<__nv_bfloat16*>(sm + OFF_BL + n * 144 + k * 2) = l;
    }
    if (tid < 64) {
        reinterpret_cast<float*>(sm + OFF_DW2)[tid] = dw2[tid];
        reinterpret_cast<float*>(sm + OFF_DB1)[tid] = db1[tid];
    }

    // ---- stage Prod tiles only, row-coalesced ----
    {
        int half = lane >> 4;
        int c    = lane & 15;
        #pragma unroll
        for (int t = 0; t < 8; t++) {
            int p_local = wid * 16 + t * 2 + half;
            int p = blockIdx.x * 128 + p_local;
            int pc = p < PP ? p : PP - 1;
            int i0 = idx[pc];
            int j0 = idx[PP + pc];
            float4 hi4 = reinterpret_cast<const float4*>(g_h)[i0 * 16 + c];
            float4 hj4 = reinterpret_cast<const float4*>(g_h)[j0 * 16 + c];
            float4 pr = make_float4(hi4.x * hj4.x, hi4.y * hj4.y,
                                    hi4.z * hj4.z, hi4.w * hj4.w);
            uint2 ph, pl;
            split_pack(pr.x, pr.y, ph.x, pl.x);
            split_pack(pr.z, pr.w, ph.y, pl.y);
            *reinterpret_cast<uint2*>(sm + OFF_PH + p_local * 144 + c * 8) = ph;
            *reinterpret_cast<uint2*>(sm + OFF_PL + p_local * 144 + c * 8) = pl;
        }
    }
    __syncthreads();

    int grp  = lane >> 2;
    int tig  = lane & 3;
    int r0   = wid * 16 + grp;

    const uint32_t* PH  = reinterpret_cast<const uint32_t*>(sm + OFF_PH);
    const uint32_t* PL  = reinterpret_cast<const uint32_t*>(sm + OFF_PL);
    const uint32_t* BH  = reinterpret_cast<const uint32_t*>(sm + OFF_BH);
    const uint32_t* BL  = reinterpret_cast<const uint32_t*>(sm + OFF_BL);
    const float*   sdw2 = reinterpret_cast<const float*>(sm + OFF_DW2);
    const float*   sdb1 = reinterpret_cast<const float*>(sm + OFF_DB1);

    uint32_t ah[4][4], al[4][4];
    #pragma unroll
    for (int ks = 0; ks < 4; ks++) {
        int k0 = ks * 8 + tig;
        ah[ks][0] = PH[ r0      * 36 + k0];
        ah[ks][1] = PH[(r0 + 8) * 36 + k0];
        ah[ks][2] = PH[ r0      * 36 + k0 + 4];
        ah[ks][3] = PH[(r0 + 8) * 36 + k0 + 4];
        al[ks][0] = PL[ r0      * 36 + k0];
        al[ks][1] = PL[(r0 + 8) * 36 + k0];
        al[ks][2] = PL[ r0      * 36 + k0 + 4];
        al[ks][3] = PL[(r0 + 8) * 36 + k0 + 4];
    }

    // per-fragment-row pair indices for direct UV loads
    int pA = blockIdx.x * 128 + r0;
    int pB = pA + 8;
    int pAc = pA < PP ? pA : PP - 1;
    int pBc = pB < PP ? pB : PP - 1;
    int iA = idx[pAc], jA = idx[PP + pAc];
    int iB = idx[pBc], jB = idx[PP + pBc];

    float pa = 0.0f, pb = 0.0f;
    #pragma unroll
    for (int nt = 0; nt < 8; nt++) {
        int n = nt * 8 + grp;
        int cbase = nt * 8 + tig * 2;
        float2 uA = *reinterpret_cast<const float2*>(&g_u[iA * 64 + cbase]);
        float2 vA = *reinterpret_cast<const float2*>(&g_v[jA * 64 + cbase]);
        float2 uB = *reinterpret_cast<const float2*>(&g_u[iB * 64 + cbase]);
        float2 vB = *reinterpret_cast<const float2*>(&g_v[jB * 64 + cbase]);
        float2 dbv = *reinterpret_cast<const float2*>(&sdb1[cbase]);
        float c0 = uA.x + vA.x + dbv.x, c1 = uA.y + vA.y + dbv.y;
        float c2 = uB.x + vB.x + dbv.x, c3 = uB.y + vB.y + dbv.y;
        #pragma unroll
        for (int ks = 0; ks < 4; ks++) {
            int kb = ks * 8 + tig;
            uint32_t bh0 = BH[n * 36 + kb], bh1 = BH[n * 36 + kb + 4];
            uint32_t bl0 = BL[n * 36 + kb], bl1 = BL[n * 36 + kb + 4];
            MMA16816(c0, c1, c2, c3, ah[ks], bh0, bh1);
            MMA16816(c0, c1, c2, c3, ah[ks], bl0, bl1);
            MMA16816(c0, c1, c2, c3, al[ks], bh0, bh1);
        }
        float w0 = sdw2[cbase], w1 = sdw2[cbase + 1];
        pa = fmaf(fmaxf(c0, 0.0f), w0, fmaf(fmaxf(c1, 0.0f), w1, pa));
        pb = fmaf(fmaxf(c2, 0.0f), w0, fmaf(fmaxf(c3, 0.0f), w1, pb));
    }

    pa += __shfl_xor_sync(0xffffffffu, pa, 1);
    pa += __shfl_xor_sync(0xffffffffu, pa, 2);
    pb += __shfl_xor_sync(0xffffffffu, pb, 1);
    pb += __shfl_xor_sync(0xffffffffu, pb, 2);

    if (tig == 0) {
        float bo = db2[0];
        if (pA < PP) out[pA] = pa + bo;
        if (pB < PP) out[pB] = pb + bo;
    }
}

// ---------------------------------------------------------------------------
extern "C" void kernel_launch(void* const* d_in, const int* in_sizes, int n_in,
                              void* d_out, int out_size) {
    const float* x   = (const float*)d_in[0];
    const int*   ei  = (const int*)  d_in[1];
    // d_in[2] = curvature (unused by the output)
    const int*   idx = (const int*)  d_in[3];
    const float* w1  = (const float*)d_in[4];
    const float* b1  = (const float*)d_in[5];
    const float* w2  = (const float*)d_in[6];
    const float* b2  = (const float*)d_in[7];
    const float* dw1 = (const float*)d_in[8];
    const float* db1 = (const float*)d_in[9];
    const float* dw2 = (const float*)d_in[10];
    const float* db2 = (const float*)d_in[11];
    float* out = (float*)d_out;

    cudaFuncSetAttribute(k_mlp_uv_mma, cudaFuncAttributeMaxDynamicSharedMemorySize,
                         MLP_SMEM);
    cudaFuncSetAttribute(k_pair_mma, cudaFuncAttributeMaxDynamicSharedMemorySize,
                         PAIR_SMEM);

    // CSR build
    k_zero <<<(NN + 256) / 256, 256>>>();
    k_count<<<(EE + 255) / 256, 256>>>(ei);
    k_scan1<<<NB, 1024>>>();
    k_scan2<<<1, 32>>>();
    k_scan3<<<(NN + 255) / 256, 256>>>();
    k_fill <<<(EE + 255) / 256, 256>>>(ei);

    // aggregate + node chain + pair decoder
    k_agg       <<<(NN + 15) / 16, 256>>>(x);
    k_mlp_uv_mma<<<296, 256, MLP_SMEM>>>(w1, b1, w2, b2, dw1);
    k_pair_mma  <<<(PP + 127) / 128, 256, PAIR_SMEM>>>(idx, dw1, db1, dw2, db2, out);
}